// round 2
// baseline (speedup 1.0000x reference)
#include <cuda_runtime.h>

// Problem constants
#define NB 2
#define NS 256
#define ND 256
#define NH 1024
#define NE 16
#define NK 2

constexpr int NT = NB * NS;      // 512 tokens
constexpr int NP = NT * NK;      // 1024 (token, k) pairs

// Scratch (device globals: allocation-free per harness rules)
__device__ int   g_counts[NE];
__device__ int   g_pairs[NE * NP];
__device__ float g_hidden[(size_t)NP * NH];   // 4 MB

__device__ __forceinline__ float gelu_tanh(float v) {
    // flax nn.gelu default (tanh approximation)
    const float c = 0.7978845608028654f;  // sqrt(2/pi)
    float u = c * (v + 0.044715f * v * v * v);
    return 0.5f * v * (1.0f + tanhf(u));
}

// ---------------------------------------------------------------------------
// Kernel 0: bucket the 1024 (token,k) pairs by expert. 1 block of 1024 threads.
// ---------------------------------------------------------------------------
__global__ void bucket_kernel(const int* __restrict__ expert_indices) {
    int t = threadIdx.x;                 // pair id = token*K + k = flat index
    if (t < NE) g_counts[t] = 0;
    __syncthreads();
    int e = expert_indices[t];
    int slot = atomicAdd(&g_counts[e], 1);
    g_pairs[e * NP + slot] = t;
}

// ---------------------------------------------------------------------------
// Kernel 1: hidden[pair, h] = gelu( x[token] . keys[e][h] )
// Tiled GEMM: M = 32 pairs, N = 128 h, contraction over D=256 in 64-chunks.
// grid = (NH/128, NP/32, NE), block = 256
// ---------------------------------------------------------------------------
__global__ __launch_bounds__(256) void ffn1_kernel(const float* __restrict__ x,
                                                   const float* __restrict__ keys) {
    const int e  = blockIdx.z;
    const int n  = g_counts[e];
    const int pt = blockIdx.y;
    if (pt * 32 >= n) return;
    const int hb = blockIdx.x * 128;

    __shared__ float Ks[64][136];   // [d][h], padded: conflict-free float4 reads
    __shared__ float Xs[64][32];    // [d][p]

    const int tid = threadIdx.x;
    const int tx = tid & 15;        // 8 h-columns each
    const int ty = tid >> 4;        // 2 p-rows each (ty, ty+16)

    // per-thread pair for the X tile load (column p = tid & 31, fixed)
    const int pcol = tid & 31;
    const int pidx = pt * 32 + pcol;
    const int pr_load = (pidx < n) ? g_pairs[e * NP + pidx] : -1;
    const int xrow = (pr_load >= 0) ? (pr_load >> 1) : 0;   // token = pair / K

    float acc[2][8];
    #pragma unroll
    for (int r = 0; r < 2; r++)
        #pragma unroll
        for (int j = 0; j < 8; j++) acc[r][j] = 0.0f;

    const float* kbase = keys + (size_t)e * NH * ND + (size_t)hb * ND;

    for (int d0 = 0; d0 < ND; d0 += 64) {
        // K tile: 128 h x 64 d  = 2048 float4, 8 per thread
        #pragma unroll
        for (int i = 0; i < 8; i++) {
            int lin = tid + i * 256;
            int h = lin >> 4, d4 = lin & 15;
            float4 v = *(const float4*)(kbase + (size_t)h * ND + d0 + d4 * 4);
            Ks[d4 * 4 + 0][h] = v.x;
            Ks[d4 * 4 + 1][h] = v.y;
            Ks[d4 * 4 + 2][h] = v.z;
            Ks[d4 * 4 + 3][h] = v.w;
        }
        // X tile (gathered rows): 32 p x 64 d = 512 float4, 2 per thread
        #pragma unroll
        for (int i = 0; i < 2; i++) {
            int lin = tid + i * 256;
            int d4 = lin >> 5;                  // 0..15
            float4 v = make_float4(0.f, 0.f, 0.f, 0.f);
            if (pr_load >= 0)
                v = *(const float4*)(x + (size_t)xrow * ND + d0 + d4 * 4);
            Xs[d4 * 4 + 0][pcol] = v.x;
            Xs[d4 * 4 + 1][pcol] = v.y;
            Xs[d4 * 4 + 2][pcol] = v.z;
            Xs[d4 * 4 + 3][pcol] = v.w;
        }
        __syncthreads();

        #pragma unroll 8
        for (int d = 0; d < 64; d++) {
            float a0 = Xs[d][ty];
            float a1 = Xs[d][ty + 16];
            float4 b0 = *(const float4*)(&Ks[d][tx * 8]);
            float4 b1 = *(const float4*)(&Ks[d][tx * 8 + 4]);
            acc[0][0] = fmaf(a0, b0.x, acc[0][0]);
            acc[0][1] = fmaf(a0, b0.y, acc[0][1]);
            acc[0][2] = fmaf(a0, b0.z, acc[0][2]);
            acc[0][3] = fmaf(a0, b0.w, acc[0][3]);
            acc[0][4] = fmaf(a0, b1.x, acc[0][4]);
            acc[0][5] = fmaf(a0, b1.y, acc[0][5]);
            acc[0][6] = fmaf(a0, b1.z, acc[0][6]);
            acc[0][7] = fmaf(a0, b1.w, acc[0][7]);
            acc[1][0] = fmaf(a1, b0.x, acc[1][0]);
            acc[1][1] = fmaf(a1, b0.y, acc[1][1]);
            acc[1][2] = fmaf(a1, b0.z, acc[1][2]);
            acc[1][3] = fmaf(a1, b0.w, acc[1][3]);
            acc[1][4] = fmaf(a1, b1.x, acc[1][4]);
            acc[1][5] = fmaf(a1, b1.y, acc[1][5]);
            acc[1][6] = fmaf(a1, b1.z, acc[1][6]);
            acc[1][7] = fmaf(a1, b1.w, acc[1][7]);
        }
        __syncthreads();
    }

    // Epilogue: gelu, store to hidden buffer (indexed by original pair id)
    #pragma unroll
    for (int r = 0; r < 2; r++) {
        int p  = ty + r * 16;
        int pi = pt * 32 + p;
        if (pi < n) {
            int pr = g_pairs[e * NP + pi];
            float* hp = g_hidden + (size_t)pr * NH + hb + tx * 8;
            float4 o0, o1;
            o0.x = gelu_tanh(acc[r][0]);
            o0.y = gelu_tanh(acc[r][1]);
            o0.z = gelu_tanh(acc[r][2]);
            o0.w = gelu_tanh(acc[r][3]);
            o1.x = gelu_tanh(acc[r][4]);
            o1.y = gelu_tanh(acc[r][5]);
            o1.z = gelu_tanh(acc[r][6]);
            o1.w = gelu_tanh(acc[r][7]);
            *(float4*)(hp)     = o0;
            *(float4*)(hp + 4) = o1;
        }
    }
}

// ---------------------------------------------------------------------------
// Kernel 2: out[token, d] += w * sum_h values[e][d][h] * hidden[pair][h]
// Tiled GEMM: M = 32 pairs, N = 128 d, contraction over H=1024 split 4-way
// across CTAs (atomicAdd accumulation) for occupancy.
// grid = (2*4, NP/32, NE), block = 256.  blockIdx.x: bit0 -> d-tile, bits1+ -> h-split
// ---------------------------------------------------------------------------
__global__ __launch_bounds__(256) void ffn2_kernel(const float* __restrict__ values,
                                                   const float* __restrict__ expert_weights,
                                                   float* __restrict__ out) {
    const int e  = blockIdx.z;
    const int n  = g_counts[e];
    const int pt = blockIdx.y;
    if (pt * 32 >= n) return;
    const int db = (blockIdx.x & 1) * 128;
    const int hs = blockIdx.x >> 1;            // 0..3, each covers 256 of H

    __shared__ float Vs[64][136];   // [h][d]
    __shared__ float Hs[64][32];    // [h][p]

    const int tid = threadIdx.x;
    const int tx = tid & 15;
    const int ty = tid >> 4;

    const int pcol = tid & 31;
    const int pidx = pt * 32 + pcol;
    const int pr_load = (pidx < n) ? g_pairs[e * NP + pidx] : -1;

    float acc[2][8];
    #pragma unroll
    for (int r = 0; r < 2; r++)
        #pragma unroll
        for (int j = 0; j < 8; j++) acc[r][j] = 0.0f;

    const float* vbase = values + (size_t)e * ND * NH + (size_t)db * NH;

    const int h_begin = hs * 256;
    for (int h0 = h_begin; h0 < h_begin + 256; h0 += 64) {
        // V tile: 128 d x 64 h = 2048 float4
        #pragma unroll
        for (int i = 0; i < 8; i++) {
            int lin = tid + i * 256;
            int d = lin >> 4, h4 = lin & 15;
            float4 v = *(const float4*)(vbase + (size_t)d * NH + h0 + h4 * 4);
            Vs[h4 * 4 + 0][d] = v.x;
            Vs[h4 * 4 + 1][d] = v.y;
            Vs[h4 * 4 + 2][d] = v.z;
            Vs[h4 * 4 + 3][d] = v.w;
        }
        // hidden tile: 32 p x 64 h
        #pragma unroll
        for (int i = 0; i < 2; i++) {
            int lin = tid + i * 256;
            int h4 = lin >> 5;
            float4 v = make_float4(0.f, 0.f, 0.f, 0.f);
            if (pr_load >= 0)
                v = *(const float4*)(g_hidden + (size_t)pr_load * NH + h0 + h4 * 4);
            Hs[h4 * 4 + 0][pcol] = v.x;
            Hs[h4 * 4 + 1][pcol] = v.y;
            Hs[h4 * 4 + 2][pcol] = v.z;
            Hs[h4 * 4 + 3][pcol] = v.w;
        }
        __syncthreads();

        #pragma unroll 8
        for (int h = 0; h < 64; h++) {
            float a0 = Hs[h][ty];
            float a1 = Hs[h][ty + 16];
            float4 b0 = *(const float4*)(&Vs[h][tx * 8]);
            float4 b1 = *(const float4*)(&Vs[h][tx * 8 + 4]);
            acc[0][0] = fmaf(a0, b0.x, acc[0][0]);
            acc[0][1] = fmaf(a0, b0.y, acc[0][1]);
            acc[0][2] = fmaf(a0, b0.z, acc[0][2]);
            acc[0][3] = fmaf(a0, b0.w, acc[0][3]);
            acc[0][4] = fmaf(a0, b1.x, acc[0][4]);
            acc[0][5] = fmaf(a0, b1.y, acc[0][5]);
            acc[0][6] = fmaf(a0, b1.z, acc[0][6]);
            acc[0][7] = fmaf(a0, b1.w, acc[0][7]);
            acc[1][0] = fmaf(a1, b0.x, acc[1][0]);
            acc[1][1] = fmaf(a1, b0.y, acc[1][1]);
            acc[1][2] = fmaf(a1, b0.z, acc[1][2]);
            acc[1][3] = fmaf(a1, b0.w, acc[1][3]);
            acc[1][4] = fmaf(a1, b1.x, acc[1][4]);
            acc[1][5] = fmaf(a1, b1.y, acc[1][5]);
            acc[1][6] = fmaf(a1, b1.z, acc[1][6]);
            acc[1][7] = fmaf(a1, b1.w, acc[1][7]);
        }
        __syncthreads();
    }

    // Epilogue: weighted atomic accumulation into out
    #pragma unroll
    for (int r = 0; r < 2; r++) {
        int p  = ty + r * 16;
        int pi = pt * 32 + p;
        if (pi < n) {
            int pr = g_pairs[e * NP + pi];
            int token = pr >> 1;                // pair / K
            float w = expert_weights[pr];       // flat [B,S,K] index == pair id
            float* op = out + (size_t)token * ND + db + tx * 8;
            #pragma unroll
            for (int j = 0; j < 8; j++)
                atomicAdd(op + j, w * acc[r][j]);
        }
    }
}

extern "C" void kernel_launch(void* const* d_in, const int* in_sizes, int n_in,
                              void* d_out, int out_size) {
    const float* x              = (const float*)d_in[0];
    const float* keys           = (const float*)d_in[1];
    const float* values         = (const float*)d_in[2];
    const float* expert_weights = (const float*)d_in[3];
    const int*   expert_indices = (const int*)d_in[4];
    float* out = (float*)d_out;

    cudaMemsetAsync(out, 0, (size_t)out_size * sizeof(float));

    bucket_kernel<<<1, NP>>>(expert_indices);

    dim3 g1(NH / 128, NP / 32, NE);     // (8, 32, 16)
    ffn1_kernel<<<g1, 256>>>(x, keys);

    dim3 g2(2 * 4, NP / 32, NE);        // (8, 32, 16)
    ffn2_kernel<<<g2, 256>>>(values, expert_weights, out);
}

// round 3
// speedup vs baseline: 2.5196x; 2.5196x over previous
#include <cuda_runtime.h>

// Problem constants
#define NB 2
#define NS 256
#define ND 256
#define NH 1024
#define NE 16
#define NK 2

constexpr int NT = NB * NS;      // 512 tokens
constexpr int NP = NT * NK;      // 1024 (token, k) pairs

// Scratch (device globals: allocation-free per harness rules)
__device__ int   g_counts[NE];
__device__ int   g_pairs[NE * NP];
__device__ float g_hidden[(size_t)NP * NH];   // 4 MB

__device__ __forceinline__ float gelu_tanh(float v) {
    // flax nn.gelu default (tanh approximation)
    const float c = 0.7978845608028654f;  // sqrt(2/pi)
    float u = c * (v + 0.044715f * v * v * v);
    return 0.5f * v * (1.0f + tanhf(u));
}

// ---------------------------------------------------------------------------
// Kernel 0: bucket the 1024 (token,k) pairs by expert. 1 block of 1024 threads.
// ---------------------------------------------------------------------------
__global__ void bucket_kernel(const int* __restrict__ expert_indices) {
    int t = threadIdx.x;                 // pair id = token*K + k = flat index
    if (t < NE) g_counts[t] = 0;
    __syncthreads();
    int e = expert_indices[t];
    int slot = atomicAdd(&g_counts[e], 1);
    g_pairs[e * NP + slot] = t;
}

// ---------------------------------------------------------------------------
// Kernel 1: hidden[pair, h] = gelu( x[token] . keys[e][h] )
// Tile: 32 pairs x 128 h, contraction over D=256 in 64-chunks.
// Thread map: tx = tid&7 -> 4 pairs (float4 from Xs, conflict-free),
//             ty = tid>>3 -> 4 consecutive h (scalar broadcast from Ks).
// grid = (NH/128, NP/32, NE), block = 256
// ---------------------------------------------------------------------------
__global__ __launch_bounds__(256) void ffn1_kernel(const float* __restrict__ x,
                                                   const float* __restrict__ keys) {
    const int e  = blockIdx.z;
    const int n  = g_counts[e];
    const int pt = blockIdx.y;
    if (pt * 32 >= n) return;
    const int hb = blockIdx.x * 128;

    __shared__ float Ks[64][129];               // [d][h], stride 129: 2-way store conflicts
    __shared__ __align__(16) float Xs[64][32];  // [d][p], row = 128B: conflict-free

    const int tid = threadIdx.x;
    const int tx = tid & 7;         // pair group: pairs tx*4 .. tx*4+3
    const int ty = tid >> 3;        // h group: h ty*4 .. ty*4+3 (0..31 -> 128 h)

    // per-thread pair for the X tile load (column p = tid & 31, fixed)
    const int pcol = tid & 31;
    const int pidx = pt * 32 + pcol;
    const int pr_load = (pidx < n) ? g_pairs[e * NP + pidx] : -1;
    const int xrow = (pr_load >= 0) ? (pr_load >> 1) : 0;   // token = pair / K

    float acc[4][4];                // [h_j][p_i]
    #pragma unroll
    for (int j = 0; j < 4; j++)
        #pragma unroll
        for (int i = 0; i < 4; i++) acc[j][i] = 0.0f;

    const float* kbase = keys + (size_t)e * NH * ND + (size_t)hb * ND;

    for (int d0 = 0; d0 < ND; d0 += 64) {
        // K tile: 128 h x 64 d = 2048 float4, 8 per thread (transpose into [d][h])
        #pragma unroll
        for (int i = 0; i < 8; i++) {
            int lin = tid + i * 256;
            int h = lin >> 4, d4 = lin & 15;
            float4 v = *(const float4*)(kbase + (size_t)h * ND + d0 + d4 * 4);
            Ks[d4 * 4 + 0][h] = v.x;
            Ks[d4 * 4 + 1][h] = v.y;
            Ks[d4 * 4 + 2][h] = v.z;
            Ks[d4 * 4 + 3][h] = v.w;
        }
        // X tile (gathered rows): 32 p x 64 d = 512 float4, 2 per thread
        #pragma unroll
        for (int i = 0; i < 2; i++) {
            int lin = tid + i * 256;
            int d4 = lin >> 5;                  // 0..15
            float4 v = make_float4(0.f, 0.f, 0.f, 0.f);
            if (pr_load >= 0)
                v = *(const float4*)(x + (size_t)xrow * ND + d0 + d4 * 4);
            Xs[d4 * 4 + 0][pcol] = v.x;
            Xs[d4 * 4 + 1][pcol] = v.y;
            Xs[d4 * 4 + 2][pcol] = v.z;
            Xs[d4 * 4 + 3][pcol] = v.w;
        }
        __syncthreads();

        #pragma unroll 8
        for (int d = 0; d < 64; d++) {
            float4 a = *(const float4*)(&Xs[d][tx * 4]);   // 4 pairs, conflict-free
            float b0 = Ks[d][ty * 4 + 0];                  // 4 h, bank-distinct broadcast
            float b1 = Ks[d][ty * 4 + 1];
            float b2 = Ks[d][ty * 4 + 2];
            float b3 = Ks[d][ty * 4 + 3];
            acc[0][0] = fmaf(b0, a.x, acc[0][0]);
            acc[0][1] = fmaf(b0, a.y, acc[0][1]);
            acc[0][2] = fmaf(b0, a.z, acc[0][2]);
            acc[0][3] = fmaf(b0, a.w, acc[0][3]);
            acc[1][0] = fmaf(b1, a.x, acc[1][0]);
            acc[1][1] = fmaf(b1, a.y, acc[1][1]);
            acc[1][2] = fmaf(b1, a.z, acc[1][2]);
            acc[1][3] = fmaf(b1, a.w, acc[1][3]);
            acc[2][0] = fmaf(b2, a.x, acc[2][0]);
            acc[2][1] = fmaf(b2, a.y, acc[2][1]);
            acc[2][2] = fmaf(b2, a.z, acc[2][2]);
            acc[2][3] = fmaf(b2, a.w, acc[2][3]);
            acc[3][0] = fmaf(b3, a.x, acc[3][0]);
            acc[3][1] = fmaf(b3, a.y, acc[3][1]);
            acc[3][2] = fmaf(b3, a.z, acc[3][2]);
            acc[3][3] = fmaf(b3, a.w, acc[3][3]);
        }
        __syncthreads();
    }

    // Epilogue: gelu, float4 store per pair (4 consecutive h per thread)
    #pragma unroll
    for (int i = 0; i < 4; i++) {
        int pi = pt * 32 + tx * 4 + i;
        if (pi < n) {
            int pr = g_pairs[e * NP + pi];
            float4 o;
            o.x = gelu_tanh(acc[0][i]);
            o.y = gelu_tanh(acc[1][i]);
            o.z = gelu_tanh(acc[2][i]);
            o.w = gelu_tanh(acc[3][i]);
            *(float4*)(g_hidden + (size_t)pr * NH + hb + ty * 4) = o;
        }
    }
}

// ---------------------------------------------------------------------------
// Kernel 2: out[token, d] += w * sum_h values[e][d][h] * hidden[pair][h]
// Tile: 32 pairs x 128 d, contraction over H=1024 split 4-way across CTAs.
// Thread map: tx = tid&7 -> 4 pairs, ty = tid>>3 -> 4 consecutive d.
// grid = (2*4, NP/32, NE), block = 256.  blockIdx.x: bit0 -> d-tile, bits1+ -> h-split
// ---------------------------------------------------------------------------
__global__ __launch_bounds__(256) void ffn2_kernel(const float* __restrict__ values,
                                                   const float* __restrict__ expert_weights,
                                                   float* __restrict__ out) {
    const int e  = blockIdx.z;
    const int n  = g_counts[e];
    const int pt = blockIdx.y;
    if (pt * 32 >= n) return;
    const int db = (blockIdx.x & 1) * 128;
    const int hs = blockIdx.x >> 1;            // 0..3, each covers 256 of H

    __shared__ float Vs[64][129];               // [h][d], stride 129
    __shared__ __align__(16) float Hs[64][32];  // [h][p]

    const int tid = threadIdx.x;
    const int tx = tid & 7;
    const int ty = tid >> 3;

    const int pcol = tid & 31;
    const int pidx = pt * 32 + pcol;
    const int pr_load = (pidx < n) ? g_pairs[e * NP + pidx] : -1;

    float acc[4][4];                // [d_j][p_i]
    #pragma unroll
    for (int j = 0; j < 4; j++)
        #pragma unroll
        for (int i = 0; i < 4; i++) acc[j][i] = 0.0f;

    const float* vbase = values + (size_t)e * ND * NH + (size_t)db * NH;

    const int h_begin = hs * 256;
    for (int h0 = h_begin; h0 < h_begin + 256; h0 += 64) {
        // V tile: 128 d x 64 h = 2048 float4 (transpose into [h][d])
        #pragma unroll
        for (int i = 0; i < 8; i++) {
            int lin = tid + i * 256;
            int d = lin >> 4, h4 = lin & 15;
            float4 v = *(const float4*)(vbase + (size_t)d * NH + h0 + h4 * 4);
            Vs[h4 * 4 + 0][d] = v.x;
            Vs[h4 * 4 + 1][d] = v.y;
            Vs[h4 * 4 + 2][d] = v.z;
            Vs[h4 * 4 + 3][d] = v.w;
        }
        // hidden tile: 32 p x 64 h
        #pragma unroll
        for (int i = 0; i < 2; i++) {
            int lin = tid + i * 256;
            int h4 = lin >> 5;
            float4 v = make_float4(0.f, 0.f, 0.f, 0.f);
            if (pr_load >= 0)
                v = *(const float4*)(g_hidden + (size_t)pr_load * NH + h0 + h4 * 4);
            Hs[h4 * 4 + 0][pcol] = v.x;
            Hs[h4 * 4 + 1][pcol] = v.y;
            Hs[h4 * 4 + 2][pcol] = v.z;
            Hs[h4 * 4 + 3][pcol] = v.w;
        }
        __syncthreads();

        #pragma unroll 8
        for (int h = 0; h < 64; h++) {
            float4 a = *(const float4*)(&Hs[h][tx * 4]);
            float b0 = Vs[h][ty * 4 + 0];
            float b1 = Vs[h][ty * 4 + 1];
            float b2 = Vs[h][ty * 4 + 2];
            float b3 = Vs[h][ty * 4 + 3];
            acc[0][0] = fmaf(b0, a.x, acc[0][0]);
            acc[0][1] = fmaf(b0, a.y, acc[0][1]);
            acc[0][2] = fmaf(b0, a.z, acc[0][2]);
            acc[0][3] = fmaf(b0, a.w, acc[0][3]);
            acc[1][0] = fmaf(b1, a.x, acc[1][0]);
            acc[1][1] = fmaf(b1, a.y, acc[1][1]);
            acc[1][2] = fmaf(b1, a.z, acc[1][2]);
            acc[1][3] = fmaf(b1, a.w, acc[1][3]);
            acc[2][0] = fmaf(b2, a.x, acc[2][0]);
            acc[2][1] = fmaf(b2, a.y, acc[2][1]);
            acc[2][2] = fmaf(b2, a.z, acc[2][2]);
            acc[2][3] = fmaf(b2, a.w, acc[2][3]);
            acc[3][0] = fmaf(b3, a.x, acc[3][0]);
            acc[3][1] = fmaf(b3, a.y, acc[3][1]);
            acc[3][2] = fmaf(b3, a.z, acc[3][2]);
            acc[3][3] = fmaf(b3, a.w, acc[3][3]);
        }
        __syncthreads();
    }

    // Epilogue: weighted atomic accumulation into out
    #pragma unroll
    for (int i = 0; i < 4; i++) {
        int pi = pt * 32 + tx * 4 + i;
        if (pi < n) {
            int pr = g_pairs[e * NP + pi];
            int token = pr >> 1;                // pair / K
            float w = expert_weights[pr];       // flat [B,S,K] index == pair id
            float* op = out + (size_t)token * ND + db + ty * 4;
            atomicAdd(op + 0, w * acc[0][i]);
            atomicAdd(op + 1, w * acc[1][i]);
            atomicAdd(op + 2, w * acc[2][i]);
            atomicAdd(op + 3, w * acc[3][i]);
        }
    }
}

extern "C" void kernel_launch(void* const* d_in, const int* in_sizes, int n_in,
                              void* d_out, int out_size) {
    const float* x              = (const float*)d_in[0];
    const float* keys           = (const float*)d_in[1];
    const float* values         = (const float*)d_in[2];
    const float* expert_weights = (const float*)d_in[3];
    const int*   expert_indices = (const int*)d_in[4];
    float* out = (float*)d_out;

    cudaMemsetAsync(out, 0, (size_t)out_size * sizeof(float));

    bucket_kernel<<<1, NP>>>(expert_indices);

    dim3 g1(NH / 128, NP / 32, NE);     // (8, 32, 16)
    ffn1_kernel<<<g1, 256>>>(x, keys);

    dim3 g2(2 * 4, NP / 32, NE);        // (8, 32, 16)
    ffn2_kernel<<<g2, 256>>>(values, expert_weights, out);
}

// round 4
// speedup vs baseline: 2.5349x; 1.0061x over previous
#include <cuda_runtime.h>

// Problem constants
#define NB 2
#define NS 256
#define ND 256
#define NH 1024
#define NE 16
#define NK 2

constexpr int NT = NB * NS;      // 512 tokens
constexpr int NP = NT * NK;      // 1024 (token, k) pairs

// Scratch (device globals: allocation-free per harness rules)
__device__ int   g_counts[NE];
__device__ int   g_pairs[NE * NP];
__device__ float g_hidden[(size_t)NP * NH];   // 4 MB

__device__ __forceinline__ float gelu_tanh(float v) {
    // flax nn.gelu default (tanh approximation)
    const float c = 0.7978845608028654f;  // sqrt(2/pi)
    float u = c * (v + 0.044715f * v * v * v);
    return 0.5f * v * (1.0f + tanhf(u));
}

// Packed fp32x2 helpers (Blackwell f32x2 path; IEEE fp32 per lane)
#define FMA2(acc, b2, a2) \
    asm("fma.rn.f32x2 %0, %1, %2, %0;" : "+l"(acc) : "l"(b2), "l"(a2))
#define PACK2(out, f) \
    asm("mov.b64 %0, {%1, %1};" : "=l"(out) : "f"(f))
#define UNPACK2(lo, hi, in) \
    asm("mov.b64 {%0, %1}, %2;" : "=f"(lo), "=f"(hi) : "l"(in))

// ---------------------------------------------------------------------------
// Kernel 0: zero the output AND bucket the 1024 (token,k) pairs by expert.
// grid = 128 blocks x 1024 threads. All blocks zero a slice of out; block 0
// also does the bucketing. (Single kernel keeps the launch count at 3/call.)
// ---------------------------------------------------------------------------
__global__ void init_kernel(const int* __restrict__ expert_indices,
                            float* __restrict__ out) {
    int tid = threadIdx.x;
    out[blockIdx.x * 1024 + tid] = 0.0f;     // 128*1024 == NT*ND exactly

    if (blockIdx.x == 0) {
        if (tid < NE) g_counts[tid] = 0;
        __syncthreads();
        int e = expert_indices[tid];         // pair id == flat [B,S,K] index
        int slot = atomicAdd(&g_counts[e], 1);
        g_pairs[e * NP + slot] = tid;
    }
}

// ---------------------------------------------------------------------------
// Kernel 1: hidden[pair, h] = gelu( x[token] . keys[e][h] )
// Tile: 32 pairs x 128 h, contraction over D=256 in 64-chunks.
// tx = tid&7 -> 4 pairs (2x f32x2 from Xs), ty = tid>>3 -> 4 consecutive h.
// grid = (NH/128, NP/32, NE), block = 256
// ---------------------------------------------------------------------------
__global__ __launch_bounds__(256) void ffn1_kernel(const float* __restrict__ x,
                                                   const float* __restrict__ keys) {
    const int e  = blockIdx.z;
    const int n  = g_counts[e];
    const int pt = blockIdx.y;
    if (pt * 32 >= n) return;
    const int hb = blockIdx.x * 128;

    __shared__ float Ks[64][129];               // [d][h], stride 129: 2-way store conflicts
    __shared__ __align__(16) float Xs[64][32];  // [d][p], row = 128B: conflict-free

    const int tid = threadIdx.x;
    const int tx = tid & 7;         // pair group: pairs tx*4 .. tx*4+3
    const int ty = tid >> 3;        // h group: h ty*4 .. ty*4+3

    const int pcol = tid & 31;
    const int pidx = pt * 32 + pcol;
    const int pr_load = (pidx < n) ? g_pairs[e * NP + pidx] : -1;
    const int xrow = (pr_load >= 0) ? (pr_load >> 1) : 0;   // token = pair / K

    // acc2[j][g]: h = ty*4+j, packed pairs (2g, 2g+1)
    unsigned long long acc2[4][2];
    #pragma unroll
    for (int j = 0; j < 4; j++) { acc2[j][0] = 0ull; acc2[j][1] = 0ull; }

    const float* kbase = keys + (size_t)e * NH * ND + (size_t)hb * ND;

    for (int d0 = 0; d0 < ND; d0 += 64) {
        // K tile: 128 h x 64 d = 2048 float4, 8 per thread (transpose into [d][h])
        #pragma unroll
        for (int i = 0; i < 8; i++) {
            int lin = tid + i * 256;
            int h = lin >> 4, d4 = lin & 15;
            float4 v = *(const float4*)(kbase + (size_t)h * ND + d0 + d4 * 4);
            Ks[d4 * 4 + 0][h] = v.x;
            Ks[d4 * 4 + 1][h] = v.y;
            Ks[d4 * 4 + 2][h] = v.z;
            Ks[d4 * 4 + 3][h] = v.w;
        }
        // X tile (gathered rows): 32 p x 64 d
        #pragma unroll
        for (int i = 0; i < 2; i++) {
            int lin = tid + i * 256;
            int d4 = lin >> 5;
            float4 v = make_float4(0.f, 0.f, 0.f, 0.f);
            if (pr_load >= 0)
                v = *(const float4*)(x + (size_t)xrow * ND + d0 + d4 * 4);
            Xs[d4 * 4 + 0][pcol] = v.x;
            Xs[d4 * 4 + 1][pcol] = v.y;
            Xs[d4 * 4 + 2][pcol] = v.z;
            Xs[d4 * 4 + 3][pcol] = v.w;
        }
        __syncthreads();

        #pragma unroll 8
        for (int d = 0; d < 64; d++) {
            ulonglong2 a = *(const ulonglong2*)(&Xs[d][tx * 4]);  // 4 pairs as 2x f32x2
            float b0 = Ks[d][ty * 4 + 0];
            float b1 = Ks[d][ty * 4 + 1];
            float b2 = Ks[d][ty * 4 + 2];
            float b3 = Ks[d][ty * 4 + 3];
            unsigned long long bb0, bb1, bb2, bb3;
            PACK2(bb0, b0); PACK2(bb1, b1); PACK2(bb2, b2); PACK2(bb3, b3);
            FMA2(acc2[0][0], bb0, a.x); FMA2(acc2[0][1], bb0, a.y);
            FMA2(acc2[1][0], bb1, a.x); FMA2(acc2[1][1], bb1, a.y);
            FMA2(acc2[2][0], bb2, a.x); FMA2(acc2[2][1], bb2, a.y);
            FMA2(acc2[3][0], bb3, a.x); FMA2(acc2[3][1], bb3, a.y);
        }
        __syncthreads();
    }

    // Unpack, gelu, float4 store per pair (4 consecutive h per thread)
    float accf[4][4];
    #pragma unroll
    for (int j = 0; j < 4; j++) {
        UNPACK2(accf[j][0], accf[j][1], acc2[j][0]);
        UNPACK2(accf[j][2], accf[j][3], acc2[j][1]);
    }
    #pragma unroll
    for (int i = 0; i < 4; i++) {
        int pi = pt * 32 + tx * 4 + i;
        if (pi < n) {
            int pr = g_pairs[e * NP + pi];
            float4 o;
            o.x = gelu_tanh(accf[0][i]);
            o.y = gelu_tanh(accf[1][i]);
            o.z = gelu_tanh(accf[2][i]);
            o.w = gelu_tanh(accf[3][i]);
            *(float4*)(g_hidden + (size_t)pr * NH + hb + ty * 4) = o;
        }
    }
}

// ---------------------------------------------------------------------------
// Kernel 2: out[token, d] += w * sum_h values[e][d][h] * hidden[pair][h]
// Tile: 32 pairs x 128 d, contraction over H=1024 split 4-way across CTAs.
// tx = tid&7 -> 4 pairs, ty = tid>>3 -> 4 consecutive d.
// grid = (2*4, NP/32, NE), block = 256.  blockIdx.x: bit0 -> d-tile, bits1+ -> h-split
// ---------------------------------------------------------------------------
__global__ __launch_bounds__(256) void ffn2_kernel(const float* __restrict__ values,
                                                   const float* __restrict__ expert_weights,
                                                   float* __restrict__ out) {
    const int e  = blockIdx.z;
    const int n  = g_counts[e];
    const int pt = blockIdx.y;
    if (pt * 32 >= n) return;
    const int db = (blockIdx.x & 1) * 128;
    const int hs = blockIdx.x >> 1;            // 0..3, each covers 256 of H

    __shared__ float Vs[64][129];               // [h][d], stride 129
    __shared__ __align__(16) float Hs[64][32];  // [h][p]

    const int tid = threadIdx.x;
    const int tx = tid & 7;
    const int ty = tid >> 3;

    const int pcol = tid & 31;
    const int pidx = pt * 32 + pcol;
    const int pr_load = (pidx < n) ? g_pairs[e * NP + pidx] : -1;

    unsigned long long acc2[4][2];              // d = ty*4+j, packed pairs (2g,2g+1)
    #pragma unroll
    for (int j = 0; j < 4; j++) { acc2[j][0] = 0ull; acc2[j][1] = 0ull; }

    const float* vbase = values + (size_t)e * ND * NH + (size_t)db * NH;

    const int h_begin = hs * 256;
    for (int h0 = h_begin; h0 < h_begin + 256; h0 += 64) {
        // V tile: 128 d x 64 h = 2048 float4 (transpose into [h][d])
        #pragma unroll
        for (int i = 0; i < 8; i++) {
            int lin = tid + i * 256;
            int d = lin >> 4, h4 = lin & 15;
            float4 v = *(const float4*)(vbase + (size_t)d * NH + h0 + h4 * 4);
            Vs[h4 * 4 + 0][d] = v.x;
            Vs[h4 * 4 + 1][d] = v.y;
            Vs[h4 * 4 + 2][d] = v.z;
            Vs[h4 * 4 + 3][d] = v.w;
        }
        // hidden tile: 32 p x 64 h
        #pragma unroll
        for (int i = 0; i < 2; i++) {
            int lin = tid + i * 256;
            int h4 = lin >> 5;
            float4 v = make_float4(0.f, 0.f, 0.f, 0.f);
            if (pr_load >= 0)
                v = *(const float4*)(g_hidden + (size_t)pr_load * NH + h0 + h4 * 4);
            Hs[h4 * 4 + 0][pcol] = v.x;
            Hs[h4 * 4 + 1][pcol] = v.y;
            Hs[h4 * 4 + 2][pcol] = v.z;
            Hs[h4 * 4 + 3][pcol] = v.w;
        }
        __syncthreads();

        #pragma unroll 8
        for (int h = 0; h < 64; h++) {
            ulonglong2 a = *(const ulonglong2*)(&Hs[h][tx * 4]);
            float b0 = Vs[h][ty * 4 + 0];
            float b1 = Vs[h][ty * 4 + 1];
            float b2 = Vs[h][ty * 4 + 2];
            float b3 = Vs[h][ty * 4 + 3];
            unsigned long long bb0, bb1, bb2, bb3;
            PACK2(bb0, b0); PACK2(bb1, b1); PACK2(bb2, b2); PACK2(bb3, b3);
            FMA2(acc2[0][0], bb0, a.x); FMA2(acc2[0][1], bb0, a.y);
            FMA2(acc2[1][0], bb1, a.x); FMA2(acc2[1][1], bb1, a.y);
            FMA2(acc2[2][0], bb2, a.x); FMA2(acc2[2][1], bb2, a.y);
            FMA2(acc2[3][0], bb3, a.x); FMA2(acc2[3][1], bb3, a.y);
        }
        __syncthreads();
    }

    // Unpack + weighted atomic accumulation into out
    float accf[4][4];
    #pragma unroll
    for (int j = 0; j < 4; j++) {
        UNPACK2(accf[j][0], accf[j][1], acc2[j][0]);
        UNPACK2(accf[j][2], accf[j][3], acc2[j][1]);
    }
    #pragma unroll
    for (int i = 0; i < 4; i++) {
        int pi = pt * 32 + tx * 4 + i;
        if (pi < n) {
            int pr = g_pairs[e * NP + pi];
            int token = pr >> 1;                // pair / K
            float w = expert_weights[pr];       // flat [B,S,K] index == pair id
            float* op = out + (size_t)token * ND + db + ty * 4;
            atomicAdd(op + 0, w * accf[0][i]);
            atomicAdd(op + 1, w * accf[1][i]);
            atomicAdd(op + 2, w * accf[2][i]);
            atomicAdd(op + 3, w * accf[3][i]);
        }
    }
}

extern "C" void kernel_launch(void* const* d_in, const int* in_sizes, int n_in,
                              void* d_out, int out_size) {
    const float* x              = (const float*)d_in[0];
    const float* keys           = (const float*)d_in[1];
    const float* values         = (const float*)d_in[2];
    const float* expert_weights = (const float*)d_in[3];
    const int*   expert_indices = (const int*)d_in[4];
    float* out = (float*)d_out;

    init_kernel<<<NT * ND / 1024, 1024>>>(expert_indices, out);  // zero + bucket

    dim3 g1(NH / 128, NP / 32, NE);     // (8, 32, 16)
    ffn1_kernel<<<g1, 256>>>(x, keys);

    dim3 g2(2 * 4, NP / 32, NE);        // (8, 32, 16)
    ffn2_kernel<<<g2, 256>>>(values, expert_weights, out);
}

// round 7
// speedup vs baseline: 3.2191x; 1.2699x over previous
#include <cuda_runtime.h>

// Problem constants
#define NB 2
#define NS 256
#define ND 256
#define NH 1024
#define NE 16
#define NK 2

constexpr int NT = NB * NS;      // 512 tokens
constexpr int NP = NT * NK;      // 1024 (token, k) pairs

// Scratch (device globals: allocation-free per harness rules)
__device__ int   g_counts[NE];
__device__ int   g_pairs[NE * NP];
__device__ float g_hidden[(size_t)NP * NH];   // 4 MB

__device__ __forceinline__ float gelu_tanh(float v) {
    const float c = 0.7978845608028654f;  // sqrt(2/pi)
    float u = c * (v + 0.044715f * v * v * v);
    return 0.5f * v * (1.0f + tanhf(u));
}

// Packed fp32x2 helpers (Blackwell f32x2; IEEE fp32 per lane)
#define FMA2(acc, b2, a2) \
    asm("fma.rn.f32x2 %0, %1, %2, %0;" : "+l"(acc) : "l"(b2), "l"(a2))
#define PACK2(out, f) \
    asm("mov.b64 %0, {%1, %1};" : "=l"(out) : "f"(f))
#define UNPACK2(lo, hi, in) \
    asm("mov.b64 {%0, %1}, %2;" : "=f"(lo), "=f"(hi) : "l"(in))

// ---------------------------------------------------------------------------
// Kernel 0: zero the output AND bucket the 1024 (token,k) pairs by expert.
// ---------------------------------------------------------------------------
__global__ void init_kernel(const int* __restrict__ expert_indices,
                            float* __restrict__ out) {
    int tid = threadIdx.x;
    out[blockIdx.x * 1024 + tid] = 0.0f;     // 128*1024 == NT*ND exactly

    if (blockIdx.x == 0) {
        if (tid < NE) g_counts[tid] = 0;
        __syncthreads();
        int e = expert_indices[tid];         // pair id == flat [B,S,K] index
        int slot = atomicAdd(&g_counts[e], 1);
        g_pairs[e * NP + slot] = tid;
    }
}

// ---------------------------------------------------------------------------
// Kernel 1: hidden[pair, h] = gelu( x[token] . keys[e][h] )
// Tile: 32 pairs x 64 h, D=256 in four 64-chunks, register-staged pipeline
// over a SINGLE smem buffer (LDG c+1 issued before compute of c; then
// sync -> STS -> sync). Block = 128 threads.
// tx = tid&7 -> 4 pairs, ty = tid>>3 (0..15) -> 4 consecutive h.
// grid = (NH/64, NP/32, NE) = (16, 32, 16)
// ---------------------------------------------------------------------------
__global__ __launch_bounds__(128) void ffn1_kernel(const float* __restrict__ x,
                                                   const float* __restrict__ keys) {
    const int e  = blockIdx.z;
    const int n  = g_counts[e];
    const int pt = blockIdx.y;
    if (pt * 32 >= n) return;
    const int hb = blockIdx.x * 64;

    __shared__ float Ks[64][65];               // [d][h] stride 65: 2-way store conflicts
    __shared__ __align__(16) float Xs[64][32]; // [d][p], row = 128B conflict-free
    // total static smem: 16,640 + 8,192 = 24,832 B (< 48 KB limit)

    const int tid = threadIdx.x;
    const int tx = tid & 7;          // 4 pairs: tx*4 ..
    const int ty = tid >> 3;         // 4 h: ty*4 .. (0..15 -> 64 h)

    const int pcol = tid & 31;
    const int pidx = pt * 32 + pcol;
    const int pr_load = (pidx < n) ? g_pairs[e * NP + pidx] : -1;
    const int xrow = (pr_load >= 0) ? (pr_load >> 1) : 0;

    const int kh = tid >> 4;         // + i*8 -> h row 0..63
    const int kd4 = tid & 15;        // d4 within chunk
    const int xd4b = tid >> 5;       // + i*4 -> d4 0..15

    const float* kbase = keys + (size_t)e * NH * ND + (size_t)hb * ND;
    const float* xbase = x + (size_t)xrow * ND;

    unsigned long long acc2[4][2];
    #pragma unroll
    for (int j = 0; j < 4; j++) { acc2[j][0] = 0ull; acc2[j][1] = 0ull; }

    float4 kreg[8], xreg[4];

    // ---- prologue: LDG + STS chunk 0 ----
    #pragma unroll
    for (int i = 0; i < 8; i++)
        kreg[i] = *(const float4*)(kbase + (size_t)(kh + i * 8) * ND + kd4 * 4);
    #pragma unroll
    for (int i = 0; i < 4; i++) {
        xreg[i] = make_float4(0.f, 0.f, 0.f, 0.f);
        if (pr_load >= 0) xreg[i] = *(const float4*)(xbase + (xd4b + i * 4) * 4);
    }
    #pragma unroll
    for (int i = 0; i < 8; i++) {
        Ks[kd4 * 4 + 0][kh + i * 8] = kreg[i].x;
        Ks[kd4 * 4 + 1][kh + i * 8] = kreg[i].y;
        Ks[kd4 * 4 + 2][kh + i * 8] = kreg[i].z;
        Ks[kd4 * 4 + 3][kh + i * 8] = kreg[i].w;
    }
    #pragma unroll
    for (int i = 0; i < 4; i++) {
        int d4 = xd4b + i * 4;
        Xs[d4 * 4 + 0][pcol] = xreg[i].x;
        Xs[d4 * 4 + 1][pcol] = xreg[i].y;
        Xs[d4 * 4 + 2][pcol] = xreg[i].z;
        Xs[d4 * 4 + 3][pcol] = xreg[i].w;
    }
    __syncthreads();

    #pragma unroll
    for (int c = 0; c < 4; c++) {
        // prefetch chunk c+1 into registers; LDG latency hidden by compute
        if (c < 3) {
            int d0 = (c + 1) * 64;
            #pragma unroll
            for (int i = 0; i < 8; i++)
                kreg[i] = *(const float4*)(kbase + (size_t)(kh + i * 8) * ND + d0 + kd4 * 4);
            #pragma unroll
            for (int i = 0; i < 4; i++)
                if (pr_load >= 0) xreg[i] = *(const float4*)(xbase + d0 + (xd4b + i * 4) * 4);
        }

        #pragma unroll 8
        for (int d = 0; d < 64; d++) {
            ulonglong2 a = *(const ulonglong2*)(&Xs[d][tx * 4]);
            float b0 = Ks[d][ty * 4 + 0];
            float b1 = Ks[d][ty * 4 + 1];
            float b2 = Ks[d][ty * 4 + 2];
            float b3 = Ks[d][ty * 4 + 3];
            unsigned long long bb0, bb1, bb2, bb3;
            PACK2(bb0, b0); PACK2(bb1, b1); PACK2(bb2, b2); PACK2(bb3, b3);
            FMA2(acc2[0][0], bb0, a.x); FMA2(acc2[0][1], bb0, a.y);
            FMA2(acc2[1][0], bb1, a.x); FMA2(acc2[1][1], bb1, a.y);
            FMA2(acc2[2][0], bb2, a.x); FMA2(acc2[2][1], bb2, a.y);
            FMA2(acc2[3][0], bb3, a.x); FMA2(acc2[3][1], bb3, a.y);
        }

        if (c < 3) {
            __syncthreads();   // all reads of the buffer done
            #pragma unroll
            for (int i = 0; i < 8; i++) {
                Ks[kd4 * 4 + 0][kh + i * 8] = kreg[i].x;
                Ks[kd4 * 4 + 1][kh + i * 8] = kreg[i].y;
                Ks[kd4 * 4 + 2][kh + i * 8] = kreg[i].z;
                Ks[kd4 * 4 + 3][kh + i * 8] = kreg[i].w;
            }
            #pragma unroll
            for (int i = 0; i < 4; i++) {
                int d4 = xd4b + i * 4;
                Xs[d4 * 4 + 0][pcol] = xreg[i].x;
                Xs[d4 * 4 + 1][pcol] = xreg[i].y;
                Xs[d4 * 4 + 2][pcol] = xreg[i].z;
                Xs[d4 * 4 + 3][pcol] = xreg[i].w;
            }
            __syncthreads();   // buffer refilled
        }
    }

    // Epilogue: unpack, gelu, float4 store per pair
    float accf[4][4];
    #pragma unroll
    for (int j = 0; j < 4; j++) {
        UNPACK2(accf[j][0], accf[j][1], acc2[j][0]);
        UNPACK2(accf[j][2], accf[j][3], acc2[j][1]);
    }
    #pragma unroll
    for (int i = 0; i < 4; i++) {
        int pi = pt * 32 + tx * 4 + i;
        if (pi < n) {
            int pr = g_pairs[e * NP + pi];
            float4 o;
            o.x = gelu_tanh(accf[0][i]);
            o.y = gelu_tanh(accf[1][i]);
            o.z = gelu_tanh(accf[2][i]);
            o.w = gelu_tanh(accf[3][i]);
            *(float4*)(g_hidden + (size_t)pr * NH + hb + ty * 4) = o;
        }
    }
}

// ---------------------------------------------------------------------------
// Kernel 2: out[token, d] += w * sum_h values[e][d][h] * hidden[pair][h]
// Tile: 32 pairs x 64 d, contraction over 256 h (this CTA's split) in four
// 64-chunks, register-staged pipeline over a single smem buffer. Block = 128.
// grid = (4 dblk * 4 hsplit, NP/32, NE) = (16, 32, 16)
// ---------------------------------------------------------------------------
__global__ __launch_bounds__(128) void ffn2_kernel(const float* __restrict__ values,
                                                   const float* __restrict__ expert_weights,
                                                   float* __restrict__ out) {
    const int e  = blockIdx.z;
    const int n  = g_counts[e];
    const int pt = blockIdx.y;
    if (pt * 32 >= n) return;
    const int db = (blockIdx.x & 3) * 64;
    const int hs = blockIdx.x >> 2;            // 0..3, each covers 256 of H

    __shared__ float Vs[64][65];               // [h][d] stride 65
    __shared__ __align__(16) float Hs[64][32]; // [h][p]

    const int tid = threadIdx.x;
    const int tx = tid & 7;
    const int ty = tid >> 3;                   // 0..15 -> 4 d each

    const int pcol = tid & 31;
    const int pidx = pt * 32 + pcol;
    const int pr_load = (pidx < n) ? g_pairs[e * NP + pidx] : -1;

    const int vd = tid >> 4;                   // + i*8 -> d row 0..63
    const int vh4 = tid & 15;
    const int hh4b = tid >> 5;                 // + i*4 -> h4 0..15

    const float* vbase = values + (size_t)e * ND * NH + (size_t)db * NH + hs * 256;
    const float* hbase = (pr_load >= 0) ? (g_hidden + (size_t)pr_load * NH + hs * 256) : g_hidden;

    unsigned long long acc2[4][2];
    #pragma unroll
    for (int j = 0; j < 4; j++) { acc2[j][0] = 0ull; acc2[j][1] = 0ull; }

    float4 vreg[8], hreg[4];

    // prologue: LDG + STS chunk 0
    #pragma unroll
    for (int i = 0; i < 8; i++)
        vreg[i] = *(const float4*)(vbase + (size_t)(vd + i * 8) * NH + vh4 * 4);
    #pragma unroll
    for (int i = 0; i < 4; i++) {
        hreg[i] = make_float4(0.f, 0.f, 0.f, 0.f);
        if (pr_load >= 0) hreg[i] = *(const float4*)(hbase + (hh4b + i * 4) * 4);
    }
    #pragma unroll
    for (int i = 0; i < 8; i++) {
        Vs[vh4 * 4 + 0][vd + i * 8] = vreg[i].x;
        Vs[vh4 * 4 + 1][vd + i * 8] = vreg[i].y;
        Vs[vh4 * 4 + 2][vd + i * 8] = vreg[i].z;
        Vs[vh4 * 4 + 3][vd + i * 8] = vreg[i].w;
    }
    #pragma unroll
    for (int i = 0; i < 4; i++) {
        int h4 = hh4b + i * 4;
        Hs[h4 * 4 + 0][pcol] = hreg[i].x;
        Hs[h4 * 4 + 1][pcol] = hreg[i].y;
        Hs[h4 * 4 + 2][pcol] = hreg[i].z;
        Hs[h4 * 4 + 3][pcol] = hreg[i].w;
    }
    __syncthreads();

    #pragma unroll
    for (int c = 0; c < 4; c++) {
        if (c < 3) {
            int h0 = (c + 1) * 64;
            #pragma unroll
            for (int i = 0; i < 8; i++)
                vreg[i] = *(const float4*)(vbase + (size_t)(vd + i * 8) * NH + h0 + vh4 * 4);
            #pragma unroll
            for (int i = 0; i < 4; i++)
                if (pr_load >= 0) hreg[i] = *(const float4*)(hbase + h0 + (hh4b + i * 4) * 4);
        }

        #pragma unroll 8
        for (int h = 0; h < 64; h++) {
            ulonglong2 a = *(const ulonglong2*)(&Hs[h][tx * 4]);
            float b0 = Vs[h][ty * 4 + 0];
            float b1 = Vs[h][ty * 4 + 1];
            float b2 = Vs[h][ty * 4 + 2];
            float b3 = Vs[h][ty * 4 + 3];
            unsigned long long bb0, bb1, bb2, bb3;
            PACK2(bb0, b0); PACK2(bb1, b1); PACK2(bb2, b2); PACK2(bb3, b3);
            FMA2(acc2[0][0], bb0, a.x); FMA2(acc2[0][1], bb0, a.y);
            FMA2(acc2[1][0], bb1, a.x); FMA2(acc2[1][1], bb1, a.y);
            FMA2(acc2[2][0], bb2, a.x); FMA2(acc2[2][1], bb2, a.y);
            FMA2(acc2[3][0], bb3, a.x); FMA2(acc2[3][1], bb3, a.y);
        }

        if (c < 3) {
            __syncthreads();
            #pragma unroll
            for (int i = 0; i < 8; i++) {
                Vs[vh4 * 4 + 0][vd + i * 8] = vreg[i].x;
                Vs[vh4 * 4 + 1][vd + i * 8] = vreg[i].y;
                Vs[vh4 * 4 + 2][vd + i * 8] = vreg[i].z;
                Vs[vh4 * 4 + 3][vd + i * 8] = vreg[i].w;
            }
            #pragma unroll
            for (int i = 0; i < 4; i++) {
                int h4 = hh4b + i * 4;
                Hs[h4 * 4 + 0][pcol] = hreg[i].x;
                Hs[h4 * 4 + 1][pcol] = hreg[i].y;
                Hs[h4 * 4 + 2][pcol] = hreg[i].z;
                Hs[h4 * 4 + 3][pcol] = hreg[i].w;
            }
            __syncthreads();
        }
    }

    // Epilogue: unpack + weighted atomic accumulation
    float accf[4][4];
    #pragma unroll
    for (int j = 0; j < 4; j++) {
        UNPACK2(accf[j][0], accf[j][1], acc2[j][0]);
        UNPACK2(accf[j][2], accf[j][3], acc2[j][1]);
    }
    #pragma unroll
    for (int i = 0; i < 4; i++) {
        int pi = pt * 32 + tx * 4 + i;
        if (pi < n) {
            int pr = g_pairs[e * NP + pi];
            int token = pr >> 1;
            float w = expert_weights[pr];
            float* op = out + (size_t)token * ND + db + ty * 4;
            atomicAdd(op + 0, w * accf[0][i]);
            atomicAdd(op + 1, w * accf[1][i]);
            atomicAdd(op + 2, w * accf[2][i]);
            atomicAdd(op + 3, w * accf[3][i]);
        }
    }
}

extern "C" void kernel_launch(void* const* d_in, const int* in_sizes, int n_in,
                              void* d_out, int out_size) {
    const float* x              = (const float*)d_in[0];
    const float* keys           = (const float*)d_in[1];
    const float* values         = (const float*)d_in[2];
    const float* expert_weights = (const float*)d_in[3];
    const int*   expert_indices = (const int*)d_in[4];
    float* out = (float*)d_out;

    init_kernel<<<NT * ND / 1024, 1024>>>(expert_indices, out);  // zero + bucket

    dim3 g1(NH / 64, NP / 32, NE);      // (16, 32, 16)
    ffn1_kernel<<<g1, 128>>>(x, keys);

    dim3 g2(4 * 4, NP / 32, NE);        // (16, 32, 16)
    ffn2_kernel<<<g2, 128>>>(values, expert_weights, out);
}

// round 10
// speedup vs baseline: 5.2899x; 1.6433x over previous
#include <cuda_runtime.h>
#include <cstdint>

// Problem constants
#define NB 2
#define NS 256
#define ND 256
#define NH 1024
#define NE 16
#define NK 2

constexpr int NT = NB * NS;      // 512 tokens
constexpr int NP = NT * NK;      // 1024 (token, k) pairs

// Scratch (device globals: allocation-free per harness rules)
__device__ int   g_counts[NE];
__device__ int   g_pairs[NE * NP];
__device__ float g_hidden[(size_t)NP * NH];   // 4 MB

__device__ __forceinline__ float gelu_tanh(float v) {
    const float c = 0.7978845608028654f;  // sqrt(2/pi)
    float u = c * (v + 0.044715f * v * v * v);
    return 0.5f * v * (1.0f + tanhf(u));
}

// fp32 -> tf32 bits, round-to-nearest (kills truncation bias)
__device__ __forceinline__ uint32_t to_tf32(float f) {
    uint32_t r;
    asm("cvt.rna.tf32.f32 %0, %1;" : "=r"(r) : "f"(f));
    return r;
}
__device__ __forceinline__ uint4 to_tf32x4(float4 v) {
    uint4 r;
    r.x = to_tf32(v.x); r.y = to_tf32(v.y); r.z = to_tf32(v.z); r.w = to_tf32(v.w);
    return r;
}

// D(16x8) += A(16x8,row) * B(8x8,col), tf32 inputs, f32 accum. sm_80+.
__device__ __forceinline__ void mma_tf32(float* c, const uint32_t* a, const uint32_t* b) {
    asm volatile(
        "mma.sync.aligned.m16n8k8.row.col.f32.tf32.tf32.f32 "
        "{%0,%1,%2,%3}, {%4,%5,%6,%7}, {%8,%9}, {%0,%1,%2,%3};"
        : "+f"(c[0]), "+f"(c[1]), "+f"(c[2]), "+f"(c[3])
        : "r"(a[0]), "r"(a[1]), "r"(a[2]), "r"(a[3]), "r"(b[0]), "r"(b[1]));
}

// smem tile stride: 36 words = 144 B (9x16B) -> 128b STS/LDS conflict-free
#define TS 36

// ---------------------------------------------------------------------------
// Kernel 0: zero the output AND bucket the 1024 (token,k) pairs by expert.
// ---------------------------------------------------------------------------
__global__ void init_kernel(const int* __restrict__ expert_indices,
                            float* __restrict__ out) {
    int tid = threadIdx.x;
    out[blockIdx.x * 1024 + tid] = 0.0f;     // 128*1024 == NT*ND exactly

    if (blockIdx.x == 0) {
        if (tid < NE) g_counts[tid] = 0;
        __syncthreads();
        int e = expert_indices[tid];         // pair id == flat [B,S,K] index
        int slot = atomicAdd(&g_counts[e], 1);
        g_pairs[e * NP + slot] = tid;
    }
}

// ---------------------------------------------------------------------------
// Kernel 1 (mma.sync TF32): hidden[pair, h] = gelu( x[token] . keys[e][h] )
// CTA: 128 pairs x 128 h, K=D=256 in 8 chunks of 32. Block 256 (8 warps,
// warp grid 2M x 4N, warp tile 64x32).
// grid = (NH/128, 8 mtiles, NE) = (8, 8, 16)
// ---------------------------------------------------------------------------
__global__ __launch_bounds__(256) void ffn1_mma(const float* __restrict__ x,
                                                const float* __restrict__ keys) {
    const int e  = blockIdx.z;
    const int n  = g_counts[e];
    const int mt = blockIdx.y;
    if (mt * 128 >= n) return;
    const int hb = blockIdx.x * 128;

    __shared__ uint32_t As[128][TS];   // [pair][d] tf32 bits
    __shared__ uint32_t Bs[128][TS];   // [h][d]

    const int tid  = threadIdx.x;
    const int lane = tid & 31;
    const int w    = tid >> 5;
    const int wm   = (w & 1) * 64;     // warp M offset
    const int wn   = (w >> 1) * 32;    // warp N offset
    const int qr   = lane >> 2;        // quad row 0..7
    const int qc   = lane & 3;         // quad col 0..3

    // tile loads: 4 float4 per thread per tile; row = (tid>>3) + 32*i, f4 = tid&7
    const int lrow = tid >> 3;
    const int lf4  = tid & 7;

    const float* ap[4];
    #pragma unroll
    for (int i = 0; i < 4; i++) {
        int pi = mt * 128 + lrow + 32 * i;
        int pr = (pi < n) ? g_pairs[e * NP + pi] : -1;
        ap[i] = (pr >= 0) ? (x + (size_t)(pr >> 1) * ND) : nullptr;
    }
    const float* kb = keys + (size_t)e * NH * ND + (size_t)hb * ND;

    float acc[4][4][4];                // [mf][nf][c0..c3]
    #pragma unroll
    for (int mf = 0; mf < 4; mf++)
        #pragma unroll
        for (int nf = 0; nf < 4; nf++)
            #pragma unroll
            for (int j = 0; j < 4; j++) acc[mf][nf][j] = 0.0f;

    float4 ar[4], br[4];
    // prologue: LDG chunk 0
    #pragma unroll
    for (int i = 0; i < 4; i++) {
        ar[i] = ap[i] ? *(const float4*)(ap[i] + lf4 * 4) : make_float4(0, 0, 0, 0);
        br[i] = *(const float4*)(kb + (size_t)(lrow + 32 * i) * ND + lf4 * 4);
    }
    #pragma unroll
    for (int i = 0; i < 4; i++) {
        *(uint4*)&As[lrow + 32 * i][lf4 * 4] = to_tf32x4(ar[i]);
        *(uint4*)&Bs[lrow + 32 * i][lf4 * 4] = to_tf32x4(br[i]);
    }
    __syncthreads();

    for (int c = 0; c < 8; c++) {
        if (c < 7) {                   // prefetch next chunk (overlaps compute)
            int d0 = (c + 1) * 32;
            #pragma unroll
            for (int i = 0; i < 4; i++) {
                ar[i] = ap[i] ? *(const float4*)(ap[i] + d0 + lf4 * 4)
                              : make_float4(0, 0, 0, 0);
                br[i] = *(const float4*)(kb + (size_t)(lrow + 32 * i) * ND + d0 + lf4 * 4);
            }
        }

        #pragma unroll
        for (int ks = 0; ks < 4; ks++) {
            const int k0 = ks * 8 + qc;
            uint32_t af[4][4], bf[4][2];
            #pragma unroll
            for (int mf = 0; mf < 4; mf++) {
                int r = wm + mf * 16 + qr;
                af[mf][0] = As[r][k0];     af[mf][1] = As[r + 8][k0];
                af[mf][2] = As[r][k0 + 4]; af[mf][3] = As[r + 8][k0 + 4];
            }
            #pragma unroll
            for (int nf = 0; nf < 4; nf++) {
                int cn = wn + nf * 8 + qr;
                bf[nf][0] = Bs[cn][k0];
                bf[nf][1] = Bs[cn][k0 + 4];
            }
            #pragma unroll
            for (int mf = 0; mf < 4; mf++)
                #pragma unroll
                for (int nf = 0; nf < 4; nf++)
                    mma_tf32(acc[mf][nf], af[mf], bf[nf]);
        }

        if (c < 7) {
            __syncthreads();           // reads done
            #pragma unroll
            for (int i = 0; i < 4; i++) {
                *(uint4*)&As[lrow + 32 * i][lf4 * 4] = to_tf32x4(ar[i]);
                *(uint4*)&Bs[lrow + 32 * i][lf4 * 4] = to_tf32x4(br[i]);
            }
            __syncthreads();           // refilled
        }
    }

    // Epilogue: gelu + float2 stores (c0,c1)/(c2,c3) are adjacent columns
    #pragma unroll
    for (int mf = 0; mf < 4; mf++) {
        #pragma unroll
        for (int half = 0; half < 2; half++) {
            int row = wm + mf * 16 + qr + half * 8;
            int pi  = mt * 128 + row;
            if (pi < n) {
                int pr = g_pairs[e * NP + pi];
                float* hp = g_hidden + (size_t)pr * NH + hb;
                #pragma unroll
                for (int nf = 0; nf < 4; nf++) {
                    int col = wn + nf * 8 + 2 * qc;
                    float2 o;
                    o.x = gelu_tanh(acc[mf][nf][half * 2 + 0]);
                    o.y = gelu_tanh(acc[mf][nf][half * 2 + 1]);
                    *(float2*)(hp + col) = o;
                }
            }
        }
    }
}

// ---------------------------------------------------------------------------
// Kernel 2 (mma.sync TF32): out[token,d] += w * sum_h hidden[pair,h]*values[e][d][h]
// CTA: 128 pairs x 128 d, K = 512 h (its hsplit) in 16 chunks of 32.
// grid = (2 dtile * 2 hsplit, 8 mtiles, NE) = (4, 8, 16), block 256.
// ---------------------------------------------------------------------------
__global__ __launch_bounds__(256) void ffn2_mma(const float* __restrict__ values,
                                                const float* __restrict__ expert_weights,
                                                float* __restrict__ out) {
    const int e  = blockIdx.z;
    const int n  = g_counts[e];
    const int mt = blockIdx.y;
    if (mt * 128 >= n) return;
    const int db    = (blockIdx.x & 1) * 128;
    const int hbase = (blockIdx.x >> 1) * 512;

    __shared__ uint32_t As[128][TS];   // [pair][h]
    __shared__ uint32_t Bs[128][TS];   // [d][h]

    const int tid  = threadIdx.x;
    const int lane = tid & 31;
    const int w    = tid >> 5;
    const int wm   = (w & 1) * 64;
    const int wn   = (w >> 1) * 32;
    const int qr   = lane >> 2;
    const int qc   = lane & 3;

    const int lrow = tid >> 3;
    const int lf4  = tid & 7;

    const float* ap[4];
    #pragma unroll
    for (int i = 0; i < 4; i++) {
        int pi = mt * 128 + lrow + 32 * i;
        int pr = (pi < n) ? g_pairs[e * NP + pi] : -1;
        ap[i] = (pr >= 0) ? (g_hidden + (size_t)pr * NH + hbase) : nullptr;
    }
    const float* vb = values + (size_t)e * ND * NH + (size_t)db * NH + hbase;

    float acc[4][4][4];
    #pragma unroll
    for (int mf = 0; mf < 4; mf++)
        #pragma unroll
        for (int nf = 0; nf < 4; nf++)
            #pragma unroll
            for (int j = 0; j < 4; j++) acc[mf][nf][j] = 0.0f;

    float4 ar[4], br[4];
    #pragma unroll
    for (int i = 0; i < 4; i++) {
        ar[i] = ap[i] ? *(const float4*)(ap[i] + lf4 * 4) : make_float4(0, 0, 0, 0);
        br[i] = *(const float4*)(vb + (size_t)(lrow + 32 * i) * NH + lf4 * 4);
    }
    #pragma unroll
    for (int i = 0; i < 4; i++) {
        *(uint4*)&As[lrow + 32 * i][lf4 * 4] = to_tf32x4(ar[i]);
        *(uint4*)&Bs[lrow + 32 * i][lf4 * 4] = to_tf32x4(br[i]);
    }
    __syncthreads();

    for (int c = 0; c < 16; c++) {
        if (c < 15) {
            int h0 = (c + 1) * 32;
            #pragma unroll
            for (int i = 0; i < 4; i++) {
                ar[i] = ap[i] ? *(const float4*)(ap[i] + h0 + lf4 * 4)
                              : make_float4(0, 0, 0, 0);
                br[i] = *(const float4*)(vb + (size_t)(lrow + 32 * i) * NH + h0 + lf4 * 4);
            }
        }

        #pragma unroll
        for (int ks = 0; ks < 4; ks++) {
            const int k0 = ks * 8 + qc;
            uint32_t af[4][4], bf[4][2];
            #pragma unroll
            for (int mf = 0; mf < 4; mf++) {
                int r = wm + mf * 16 + qr;
                af[mf][0] = As[r][k0];     af[mf][1] = As[r + 8][k0];
                af[mf][2] = As[r][k0 + 4]; af[mf][3] = As[r + 8][k0 + 4];
            }
            #pragma unroll
            for (int nf = 0; nf < 4; nf++) {
                int cn = wn + nf * 8 + qr;
                bf[nf][0] = Bs[cn][k0];
                bf[nf][1] = Bs[cn][k0 + 4];
            }
            #pragma unroll
            for (int mf = 0; mf < 4; mf++)
                #pragma unroll
                for (int nf = 0; nf < 4; nf++)
                    mma_tf32(acc[mf][nf], af[mf], bf[nf]);
        }

        if (c < 15) {
            __syncthreads();
            #pragma unroll
            for (int i = 0; i < 4; i++) {
                *(uint4*)&As[lrow + 32 * i][lf4 * 4] = to_tf32x4(ar[i]);
                *(uint4*)&Bs[lrow + 32 * i][lf4 * 4] = to_tf32x4(br[i]);
            }
            __syncthreads();
        }
    }

    // Epilogue: weighted atomic accumulation into out
    #pragma unroll
    for (int mf = 0; mf < 4; mf++) {
        #pragma unroll
        for (int half = 0; half < 2; half++) {
            int row = wm + mf * 16 + qr + half * 8;
            int pi  = mt * 128 + row;
            if (pi < n) {
                int pr = g_pairs[e * NP + pi];
                float wgt = expert_weights[pr];       // flat [B,S,K] index == pair id
                float* op = out + (size_t)(pr >> 1) * ND + db;
                #pragma unroll
                for (int nf = 0; nf < 4; nf++) {
                    int col = wn + nf * 8 + 2 * qc;
                    atomicAdd(op + col,     wgt * acc[mf][nf][half * 2 + 0]);
                    atomicAdd(op + col + 1, wgt * acc[mf][nf][half * 2 + 1]);
                }
            }
        }
    }
}

extern "C" void kernel_launch(void* const* d_in, const int* in_sizes, int n_in,
                              void* d_out, int out_size) {
    const float* x              = (const float*)d_in[0];
    const float* keys           = (const float*)d_in[1];
    const float* values         = (const float*)d_in[2];
    const float* expert_weights = (const float*)d_in[3];
    const int*   expert_indices = (const int*)d_in[4];
    float* out = (float*)d_out;

    init_kernel<<<NT * ND / 1024, 1024>>>(expert_indices, out);  // zero + bucket

    dim3 g1(NH / 128, 8, NE);           // (8, 8, 16)
    ffn1_mma<<<g1, 256>>>(x, keys);

    dim3 g2(2 * 2, 8, NE);              // (4, 8, 16)
    ffn2_mma<<<g2, 256>>>(values, expert_weights, out);
}

// round 11
// speedup vs baseline: 6.1009x; 1.1533x over previous
#include <cuda_runtime.h>
#include <cstdint>

// Problem constants
#define NB 2
#define NS 256
#define ND 256
#define NH 1024
#define NE 16
#define NK 2

constexpr int NT = NB * NS;      // 512 tokens
constexpr int NP = NT * NK;      // 1024 (token, k) pairs

// Scratch (device globals: allocation-free per harness rules)
__device__ int   g_counts[NE];
__device__ int   g_pairs[NE * NP];
__device__ float g_hidden[(size_t)NP * NH];   // 4 MB

__device__ __forceinline__ float gelu_tanh(float v) {
    const float c = 0.7978845608028654f;  // sqrt(2/pi)
    float u = c * (v + 0.044715f * v * v * v);
    return 0.5f * v * (1.0f + tanhf(u));
}

// fp32 -> tf32 bits, round-to-nearest
__device__ __forceinline__ uint32_t to_tf32(float f) {
    uint32_t r;
    asm("cvt.rna.tf32.f32 %0, %1;" : "=r"(r) : "f"(f));
    return r;
}
__device__ __forceinline__ uint4 to_tf32x4(float4 v) {
    uint4 r;
    r.x = to_tf32(v.x); r.y = to_tf32(v.y); r.z = to_tf32(v.z); r.w = to_tf32(v.w);
    return r;
}

// D(16x8) += A(16x8,row) * B(8x8,col), tf32 inputs, f32 accum.
__device__ __forceinline__ void mma_tf32(float* c, const uint32_t* a, const uint32_t* b) {
    asm volatile(
        "mma.sync.aligned.m16n8k8.row.col.f32.tf32.tf32.f32 "
        "{%0,%1,%2,%3}, {%4,%5,%6,%7}, {%8,%9}, {%0,%1,%2,%3};"
        : "+f"(c[0]), "+f"(c[1]), "+f"(c[2]), "+f"(c[3])
        : "r"(a[0]), "r"(a[1]), "r"(a[2]), "r"(a[3]), "r"(b[0]), "r"(b[1]));
}

// smem tile stride: 36 words = 144 B (9x16B) -> 128b STS/LDS conflict-free
#define TS 36

// ---------------------------------------------------------------------------
// Kernel 0: zero the output AND bucket the 1024 (token,k) pairs by expert.
// ---------------------------------------------------------------------------
__global__ void init_kernel(const int* __restrict__ expert_indices,
                            float* __restrict__ out) {
    int tid = threadIdx.x;
    out[blockIdx.x * 1024 + tid] = 0.0f;     // 128*1024 == NT*ND exactly

    if (blockIdx.x == 0) {
        if (tid < NE) g_counts[tid] = 0;
        __syncthreads();
        int e = expert_indices[tid];         // pair id == flat [B,S,K] index
        int slot = atomicAdd(&g_counts[e], 1);
        g_pairs[e * NP + slot] = tid;
    }
}

// ---------------------------------------------------------------------------
// Kernel 1 (mma.sync TF32): hidden[pair, h] = gelu( x[token] . keys[e][h] )
// CTA: 64 pairs x 128 h, K=D=256 in 8 chunks of 32. Block 256 (8 warps,
// warp grid 2M x 4N, warp tile 32x32 -> 2 mf x 4 nf).
// grid = (NH/128, 16 mtiles, NE); inactive mtiles exit.
// ---------------------------------------------------------------------------
__global__ __launch_bounds__(256) void ffn1_mma(const float* __restrict__ x,
                                                const float* __restrict__ keys) {
    const int e  = blockIdx.z;
    const int n  = g_counts[e];
    const int mt = blockIdx.y;
    if (mt * 64 >= n) return;
    const int hb = blockIdx.x * 128;

    __shared__ uint32_t As[64][TS];    // [pair][d] tf32 bits
    __shared__ uint32_t Bs[128][TS];   // [h][d]

    const int tid  = threadIdx.x;
    const int lane = tid & 31;
    const int w    = tid >> 5;
    const int wm   = (w & 1) * 32;     // warp M offset (2 warps cover 64)
    const int wn   = (w >> 1) * 32;    // warp N offset (4 warps cover 128)
    const int qr   = lane >> 2;        // quad row 0..7
    const int qc   = lane & 3;         // quad col 0..3

    const int lrow = tid >> 3;         // 0..31
    const int lf4  = tid & 7;

    // A rows: 2 per thread (lrow, lrow+32); B rows: 4 per thread
    const float* ap[2];
    #pragma unroll
    for (int i = 0; i < 2; i++) {
        int pi = mt * 64 + lrow + 32 * i;
        int pr = (pi < n) ? g_pairs[e * NP + pi] : -1;
        ap[i] = (pr >= 0) ? (x + (size_t)(pr >> 1) * ND) : nullptr;
    }
    const float* kb = keys + (size_t)e * NH * ND + (size_t)hb * ND;

    float acc[2][4][4];                // [mf][nf][c0..c3]
    #pragma unroll
    for (int mf = 0; mf < 2; mf++)
        #pragma unroll
        for (int nf = 0; nf < 4; nf++)
            #pragma unroll
            for (int j = 0; j < 4; j++) acc[mf][nf][j] = 0.0f;

    float4 ar[2], br[4];
    #pragma unroll
    for (int i = 0; i < 2; i++)
        ar[i] = ap[i] ? *(const float4*)(ap[i] + lf4 * 4) : make_float4(0, 0, 0, 0);
    #pragma unroll
    for (int i = 0; i < 4; i++)
        br[i] = *(const float4*)(kb + (size_t)(lrow + 32 * i) * ND + lf4 * 4);
    #pragma unroll
    for (int i = 0; i < 2; i++)
        *(uint4*)&As[lrow + 32 * i][lf4 * 4] = to_tf32x4(ar[i]);
    #pragma unroll
    for (int i = 0; i < 4; i++)
        *(uint4*)&Bs[lrow + 32 * i][lf4 * 4] = to_tf32x4(br[i]);
    __syncthreads();

    for (int c = 0; c < 8; c++) {
        if (c < 7) {                   // prefetch next chunk (overlaps compute)
            int d0 = (c + 1) * 32;
            #pragma unroll
            for (int i = 0; i < 2; i++)
                ar[i] = ap[i] ? *(const float4*)(ap[i] + d0 + lf4 * 4)
                              : make_float4(0, 0, 0, 0);
            #pragma unroll
            for (int i = 0; i < 4; i++)
                br[i] = *(const float4*)(kb + (size_t)(lrow + 32 * i) * ND + d0 + lf4 * 4);
        }

        #pragma unroll
        for (int ks = 0; ks < 4; ks++) {
            const int k0 = ks * 8 + qc;
            uint32_t af[2][4], bf[4][2];
            #pragma unroll
            for (int mf = 0; mf < 2; mf++) {
                int r = wm + mf * 16 + qr;
                af[mf][0] = As[r][k0];     af[mf][1] = As[r + 8][k0];
                af[mf][2] = As[r][k0 + 4]; af[mf][3] = As[r + 8][k0 + 4];
            }
            #pragma unroll
            for (int nf = 0; nf < 4; nf++) {
                int cn = wn + nf * 8 + qr;
                bf[nf][0] = Bs[cn][k0];
                bf[nf][1] = Bs[cn][k0 + 4];
            }
            #pragma unroll
            for (int mf = 0; mf < 2; mf++)
                #pragma unroll
                for (int nf = 0; nf < 4; nf++)
                    mma_tf32(acc[mf][nf], af[mf], bf[nf]);
        }

        if (c < 7) {
            __syncthreads();
            #pragma unroll
            for (int i = 0; i < 2; i++)
                *(uint4*)&As[lrow + 32 * i][lf4 * 4] = to_tf32x4(ar[i]);
            #pragma unroll
            for (int i = 0; i < 4; i++)
                *(uint4*)&Bs[lrow + 32 * i][lf4 * 4] = to_tf32x4(br[i]);
            __syncthreads();
        }
    }

    // Epilogue: gelu + float2 stores
    #pragma unroll
    for (int mf = 0; mf < 2; mf++) {
        #pragma unroll
        for (int half = 0; half < 2; half++) {
            int row = wm + mf * 16 + qr + half * 8;
            int pi  = mt * 64 + row;
            if (pi < n) {
                int pr = g_pairs[e * NP + pi];
                float* hp = g_hidden + (size_t)pr * NH + hb;
                #pragma unroll
                for (int nf = 0; nf < 4; nf++) {
                    int col = wn + nf * 8 + 2 * qc;
                    float2 o;
                    o.x = gelu_tanh(acc[mf][nf][half * 2 + 0]);
                    o.y = gelu_tanh(acc[mf][nf][half * 2 + 1]);
                    *(float2*)(hp + col) = o;
                }
            }
        }
    }
}

// ---------------------------------------------------------------------------
// Kernel 2 (mma.sync TF32): out[token,d] += w * sum_h hidden[pair,h]*values[e][d][h]
// CTA: 64 pairs x 128 d, K = 256 h (its hsplit of 4) in 8 chunks of 32.
// grid = (2 dtile * 4 hsplit, 16 mtiles, NE), block 256.
// ---------------------------------------------------------------------------
__global__ __launch_bounds__(256) void ffn2_mma(const float* __restrict__ values,
                                                const float* __restrict__ expert_weights,
                                                float* __restrict__ out) {
    const int e  = blockIdx.z;
    const int n  = g_counts[e];
    const int mt = blockIdx.y;
    if (mt * 64 >= n) return;
    const int db    = (blockIdx.x & 1) * 128;
    const int hbase = (blockIdx.x >> 1) * 256;

    __shared__ uint32_t As[64][TS];    // [pair][h]
    __shared__ uint32_t Bs[128][TS];   // [d][h]

    const int tid  = threadIdx.x;
    const int lane = tid & 31;
    const int w    = tid >> 5;
    const int wm   = (w & 1) * 32;
    const int wn   = (w >> 1) * 32;
    const int qr   = lane >> 2;
    const int qc   = lane & 3;

    const int lrow = tid >> 3;
    const int lf4  = tid & 7;

    const float* ap[2];
    #pragma unroll
    for (int i = 0; i < 2; i++) {
        int pi = mt * 64 + lrow + 32 * i;
        int pr = (pi < n) ? g_pairs[e * NP + pi] : -1;
        ap[i] = (pr >= 0) ? (g_hidden + (size_t)pr * NH + hbase) : nullptr;
    }
    const float* vb = values + (size_t)e * ND * NH + (size_t)db * NH + hbase;

    float acc[2][4][4];
    #pragma unroll
    for (int mf = 0; mf < 2; mf++)
        #pragma unroll
        for (int nf = 0; nf < 4; nf++)
            #pragma unroll
            for (int j = 0; j < 4; j++) acc[mf][nf][j] = 0.0f;

    float4 ar[2], br[4];
    #pragma unroll
    for (int i = 0; i < 2; i++)
        ar[i] = ap[i] ? *(const float4*)(ap[i] + lf4 * 4) : make_float4(0, 0, 0, 0);
    #pragma unroll
    for (int i = 0; i < 4; i++)
        br[i] = *(const float4*)(vb + (size_t)(lrow + 32 * i) * NH + lf4 * 4);
    #pragma unroll
    for (int i = 0; i < 2; i++)
        *(uint4*)&As[lrow + 32 * i][lf4 * 4] = to_tf32x4(ar[i]);
    #pragma unroll
    for (int i = 0; i < 4; i++)
        *(uint4*)&Bs[lrow + 32 * i][lf4 * 4] = to_tf32x4(br[i]);
    __syncthreads();

    for (int c = 0; c < 8; c++) {
        if (c < 7) {
            int h0 = (c + 1) * 32;
            #pragma unroll
            for (int i = 0; i < 2; i++)
                ar[i] = ap[i] ? *(const float4*)(ap[i] + h0 + lf4 * 4)
                              : make_float4(0, 0, 0, 0);
            #pragma unroll
            for (int i = 0; i < 4; i++)
                br[i] = *(const float4*)(vb + (size_t)(lrow + 32 * i) * NH + h0 + lf4 * 4);
        }

        #pragma unroll
        for (int ks = 0; ks < 4; ks++) {
            const int k0 = ks * 8 + qc;
            uint32_t af[2][4], bf[4][2];
            #pragma unroll
            for (int mf = 0; mf < 2; mf++) {
                int r = wm + mf * 16 + qr;
                af[mf][0] = As[r][k0];     af[mf][1] = As[r + 8][k0];
                af[mf][2] = As[r][k0 + 4]; af[mf][3] = As[r + 8][k0 + 4];
            }
            #pragma unroll
            for (int nf = 0; nf < 4; nf++) {
                int cn = wn + nf * 8 + qr;
                bf[nf][0] = Bs[cn][k0];
                bf[nf][1] = Bs[cn][k0 + 4];
            }
            #pragma unroll
            for (int mf = 0; mf < 2; mf++)
                #pragma unroll
                for (int nf = 0; nf < 4; nf++)
                    mma_tf32(acc[mf][nf], af[mf], bf[nf]);
        }

        if (c < 7) {
            __syncthreads();
            #pragma unroll
            for (int i = 0; i < 2; i++)
                *(uint4*)&As[lrow + 32 * i][lf4 * 4] = to_tf32x4(ar[i]);
            #pragma unroll
            for (int i = 0; i < 4; i++)
                *(uint4*)&Bs[lrow + 32 * i][lf4 * 4] = to_tf32x4(br[i]);
            __syncthreads();
        }
    }

    // Epilogue: weighted atomic accumulation into out
    #pragma unroll
    for (int mf = 0; mf < 2; mf++) {
        #pragma unroll
        for (int half = 0; half < 2; half++) {
            int row = wm + mf * 16 + qr + half * 8;
            int pi  = mt * 64 + row;
            if (pi < n) {
                int pr = g_pairs[e * NP + pi];
                float wgt = expert_weights[pr];       // flat [B,S,K] index == pair id
                float* op = out + (size_t)(pr >> 1) * ND + db;
                #pragma unroll
                for (int nf = 0; nf < 4; nf++) {
                    int col = wn + nf * 8 + 2 * qc;
                    atomicAdd(op + col,     wgt * acc[mf][nf][half * 2 + 0]);
                    atomicAdd(op + col + 1, wgt * acc[mf][nf][half * 2 + 1]);
                }
            }
        }
    }
}

extern "C" void kernel_launch(void* const* d_in, const int* in_sizes, int n_in,
                              void* d_out, int out_size) {
    const float* x              = (const float*)d_in[0];
    const float* keys           = (const float*)d_in[1];
    const float* values         = (const float*)d_in[2];
    const float* expert_weights = (const float*)d_in[3];
    const int*   expert_indices = (const int*)d_in[4];
    float* out = (float*)d_out;

    init_kernel<<<NT * ND / 1024, 1024>>>(expert_indices, out);  // zero + bucket

    dim3 g1(NH / 128, NP / 64, NE);     // (8, 16, 16); inactive mtiles exit
    ffn1_mma<<<g1, 256>>>(x, keys);

    dim3 g2(2 * 4, NP / 64, NE);        // (8, 16, 16)
    ffn2_mma<<<g2, 256>>>(values, expert_weights, out);
}

// round 15
// speedup vs baseline: 6.1867x; 1.0141x over previous
#include <cuda_runtime.h>
#include <cstdint>

// Problem constants
#define NB 2
#define NS 256
#define ND 256
#define NH 1024
#define NE 16
#define NK 2

constexpr int NT = NB * NS;      // 512 tokens
constexpr int NP = NT * NK;      // 1024 (token, k) pairs

// Scratch (device globals: allocation-free per harness rules)
__device__ int   g_counts[NE];
__device__ int   g_pairs[NE * NP];
__device__ float g_hidden[(size_t)NP * NH];   // 4 MB

__device__ __forceinline__ float gelu_tanh(float v) {
    const float c = 0.7978845608028654f;  // sqrt(2/pi)
    float u = c * (v + 0.044715f * v * v * v);
    return 0.5f * v * (1.0f + tanhf(u));
}

// fp32 -> tf32 bits, round-to-nearest
__device__ __forceinline__ uint32_t to_tf32(float f) {
    uint32_t r;
    asm("cvt.rna.tf32.f32 %0, %1;" : "=r"(r) : "f"(f));
    return r;
}
__device__ __forceinline__ uint4 to_tf32x4(float4 v) {
    uint4 r;
    r.x = to_tf32(v.x); r.y = to_tf32(v.y); r.z = to_tf32(v.z); r.w = to_tf32(v.w);
    return r;
}

// D(16x8) += A(16x8,row) * B(8x8,col), tf32 inputs, f32 accum.
__device__ __forceinline__ void mma_tf32(float* c, const uint32_t* a, const uint32_t* b) {
    asm volatile(
        "mma.sync.aligned.m16n8k8.row.col.f32.tf32.tf32.f32 "
        "{%0,%1,%2,%3}, {%4,%5,%6,%7}, {%8,%9}, {%0,%1,%2,%3};"
        : "+f"(c[0]), "+f"(c[1]), "+f"(c[2]), "+f"(c[3])
        : "r"(a[0]), "r"(a[1]), "r"(a[2]), "r"(a[3]), "r"(b[0]), "r"(b[1]));
}

// smem tile stride: 36 words = 144 B (9x16B) -> 128b STS/LDS conflict-free
#define TS 36

// ---------------------------------------------------------------------------
// Kernel 0: zero the output AND bucket the 1024 (token,k) pairs by expert.
// ---------------------------------------------------------------------------
__global__ void init_kernel(const int* __restrict__ expert_indices,
                            float* __restrict__ out) {
    int tid = threadIdx.x;
    out[blockIdx.x * 1024 + tid] = 0.0f;     // 128*1024 == NT*ND exactly

    if (blockIdx.x == 0) {
        if (tid < NE) g_counts[tid] = 0;
        __syncthreads();
        int e = expert_indices[tid];         // pair id == flat [B,S,K] index
        int slot = atomicAdd(&g_counts[e], 1);
        g_pairs[e * NP + slot] = tid;
    }
}

// ---------------------------------------------------------------------------
// Kernel 1 (mma.sync TF32): hidden[pair, h] = gelu( x[token] . keys[e][h] )
// CTA: 64 pairs x 128 h, K=D=256 in 8 chunks of 32. Block 256 (8 warps,
// warp grid 2M x 4N, warp tile 32x32 -> 2 mf x 4 nf).
// grid = (NH/128, 16 mtiles, NE); inactive mtiles exit.
// ---------------------------------------------------------------------------
__global__ __launch_bounds__(256, 2) void ffn1_mma(const float* __restrict__ x,
                                                   const float* __restrict__ keys) {
    const int e  = blockIdx.z;
    const int n  = g_counts[e];
    const int mt = blockIdx.y;
    if (mt * 64 >= n) return;
    const int hb = blockIdx.x * 128;

    __shared__ uint32_t As[64][TS];    // [pair][d] tf32 bits
    __shared__ uint32_t Bs[128][TS];   // [h][d]

    const int tid  = threadIdx.x;
    const int lane = tid & 31;
    const int w    = tid >> 5;
    const int wm   = (w & 1) * 32;     // warp M offset (2 warps cover 64)
    const int wn   = (w >> 1) * 32;    // warp N offset (4 warps cover 128)
    const int qr   = lane >> 2;        // quad row 0..7
    const int qc   = lane & 3;         // quad col 0..3

    const int lrow = tid >> 3;         // 0..31
    const int lf4  = tid & 7;

    // A rows: 2 per thread (lrow, lrow+32); B rows: 4 per thread
    const float* ap[2];
    #pragma unroll
    for (int i = 0; i < 2; i++) {
        int pi = mt * 64 + lrow + 32 * i;
        int pr = (pi < n) ? g_pairs[e * NP + pi] : -1;
        ap[i] = (pr >= 0) ? (x + (size_t)(pr >> 1) * ND) : nullptr;
    }
    const float* kb = keys + (size_t)e * NH * ND + (size_t)hb * ND;

    float acc[2][4][4];                // [mf][nf][c0..c3]
    #pragma unroll
    for (int mf = 0; mf < 2; mf++)
        #pragma unroll
        for (int nf = 0; nf < 4; nf++)
            #pragma unroll
            for (int j = 0; j < 4; j++) acc[mf][nf][j] = 0.0f;

    float4 ar[2], br[4];
    #pragma unroll
    for (int i = 0; i < 2; i++)
        ar[i] = ap[i] ? *(const float4*)(ap[i] + lf4 * 4) : make_float4(0, 0, 0, 0);
    #pragma unroll
    for (int i = 0; i < 4; i++)
        br[i] = *(const float4*)(kb + (size_t)(lrow + 32 * i) * ND + lf4 * 4);
    #pragma unroll
    for (int i = 0; i < 2; i++)
        *(uint4*)&As[lrow + 32 * i][lf4 * 4] = to_tf32x4(ar[i]);
    #pragma unroll
    for (int i = 0; i < 4; i++)
        *(uint4*)&Bs[lrow + 32 * i][lf4 * 4] = to_tf32x4(br[i]);
    __syncthreads();

    for (int c = 0; c < 8; c++) {
        if (c < 7) {                   // prefetch next chunk (overlaps compute)
            int d0 = (c + 1) * 32;
            #pragma unroll
            for (int i = 0; i < 2; i++)
                ar[i] = ap[i] ? *(const float4*)(ap[i] + d0 + lf4 * 4)
                              : make_float4(0, 0, 0, 0);
            #pragma unroll
            for (int i = 0; i < 4; i++)
                br[i] = *(const float4*)(kb + (size_t)(lrow + 32 * i) * ND + d0 + lf4 * 4);
        }

        #pragma unroll
        for (int ks = 0; ks < 4; ks++) {
            const int k0 = ks * 8 + qc;
            uint32_t af[2][4], bf[4][2];
            #pragma unroll
            for (int mf = 0; mf < 2; mf++) {
                int r = wm + mf * 16 + qr;
                af[mf][0] = As[r][k0];     af[mf][1] = As[r + 8][k0];
                af[mf][2] = As[r][k0 + 4]; af[mf][3] = As[r + 8][k0 + 4];
            }
            #pragma unroll
            for (int nf = 0; nf < 4; nf++) {
                int cn = wn + nf * 8 + qr;
                bf[nf][0] = Bs[cn][k0];
                bf[nf][1] = Bs[cn][k0 + 4];
            }
            #pragma unroll
            for (int mf = 0; mf < 2; mf++)
                #pragma unroll
                for (int nf = 0; nf < 4; nf++)
                    mma_tf32(acc[mf][nf], af[mf], bf[nf]);
        }

        if (c < 7) {
            __syncthreads();
            #pragma unroll
            for (int i = 0; i < 2; i++)
                *(uint4*)&As[lrow + 32 * i][lf4 * 4] = to_tf32x4(ar[i]);
            #pragma unroll
            for (int i = 0; i < 4; i++)
                *(uint4*)&Bs[lrow + 32 * i][lf4 * 4] = to_tf32x4(br[i]);
            __syncthreads();
        }
    }

    // Epilogue: gelu + float2 stores
    #pragma unroll
    for (int mf = 0; mf < 2; mf++) {
        #pragma unroll
        for (int half = 0; half < 2; half++) {
            int row = wm + mf * 16 + qr + half * 8;
            int pi  = mt * 64 + row;
            if (pi < n) {
                int pr = g_pairs[e * NP + pi];
                float* hp = g_hidden + (size_t)pr * NH + hb;
                #pragma unroll
                for (int nf = 0; nf < 4; nf++) {
                    int col = wn + nf * 8 + 2 * qc;
                    float2 o;
                    o.x = gelu_tanh(acc[mf][nf][half * 2 + 0]);
                    o.y = gelu_tanh(acc[mf][nf][half * 2 + 1]);
                    *(float2*)(hp + col) = o;
                }
            }
        }
    }
}

// ---------------------------------------------------------------------------
// Kernel 2 (mma.sync TF32): out[token,d] += w * sum_h hidden[pair,h]*values[e][d][h]
// CTA: 64 pairs x 128 d, K = 256 h (its hsplit of 4) in 8 chunks of 32.
// grid = (2 dtile * 4 hsplit, 16 mtiles, NE), block 256.
// ---------------------------------------------------------------------------
__global__ __launch_bounds__(256, 2) void ffn2_mma(const float* __restrict__ values,
                                                   const float* __restrict__ expert_weights,
                                                   float* __restrict__ out) {
    const int e  = blockIdx.z;
    const int n  = g_counts[e];
    const int mt = blockIdx.y;
    if (mt * 64 >= n) return;
    const int db    = (blockIdx.x & 1) * 128;
    const int hbase = (blockIdx.x >> 1) * 256;

    __shared__ uint32_t As[64][TS];    // [pair][h]
    __shared__ uint32_t Bs[128][TS];   // [d][h]

    const int tid  = threadIdx.x;
    const int lane = tid & 31;
    const int w    = tid >> 5;
    const int wm   = (w & 1) * 32;
    const int wn   = (w >> 1) * 32;
    const int qr   = lane >> 2;
    const int qc   = lane & 3;

    const int lrow = tid >> 3;
    const int lf4  = tid & 7;

    const float* ap[2];
    #pragma unroll
    for (int i = 0; i < 2; i++) {
        int pi = mt * 64 + lrow + 32 * i;
        int pr = (pi < n) ? g_pairs[e * NP + pi] : -1;
        ap[i] = (pr >= 0) ? (g_hidden + (size_t)pr * NH + hbase) : nullptr;
    }
    const float* vb = values + (size_t)e * ND * NH + (size_t)db * NH + hbase;

    float acc[2][4][4];
    #pragma unroll
    for (int mf = 0; mf < 2; mf++)
        #pragma unroll
        for (int nf = 0; nf < 4; nf++)
            #pragma unroll
            for (int j = 0; j < 4; j++) acc[mf][nf][j] = 0.0f;

    float4 ar[2], br[4];
    #pragma unroll
    for (int i = 0; i < 2; i++)
        ar[i] = ap[i] ? *(const float4*)(ap[i] + lf4 * 4) : make_float4(0, 0, 0, 0);
    #pragma unroll
    for (int i = 0; i < 4; i++)
        br[i] = *(const float4*)(vb + (size_t)(lrow + 32 * i) * NH + lf4 * 4);
    #pragma unroll
    for (int i = 0; i < 2; i++)
        *(uint4*)&As[lrow + 32 * i][lf4 * 4] = to_tf32x4(ar[i]);
    #pragma unroll
    for (int i = 0; i < 4; i++)
        *(uint4*)&Bs[lrow + 32 * i][lf4 * 4] = to_tf32x4(br[i]);
    __syncthreads();

    for (int c = 0; c < 8; c++) {
        if (c < 7) {
            int h0 = (c + 1) * 32;
            #pragma unroll
            for (int i = 0; i < 2; i++)
                ar[i] = ap[i] ? *(const float4*)(ap[i] + h0 + lf4 * 4)
                              : make_float4(0, 0, 0, 0);
            #pragma unroll
            for (int i = 0; i < 4; i++)
                br[i] = *(const float4*)(vb + (size_t)(lrow + 32 * i) * NH + h0 + lf4 * 4);
        }

        #pragma unroll
        for (int ks = 0; ks < 4; ks++) {
            const int k0 = ks * 8 + qc;
            uint32_t af[2][4], bf[4][2];
            #pragma unroll
            for (int mf = 0; mf < 2; mf++) {
                int r = wm + mf * 16 + qr;
                af[mf][0] = As[r][k0];     af[mf][1] = As[r + 8][k0];
                af[mf][2] = As[r][k0 + 4]; af[mf][3] = As[r + 8][k0 + 4];
            }
            #pragma unroll
            for (int nf = 0; nf < 4; nf++) {
                int cn = wn + nf * 8 + qr;
                bf[nf][0] = Bs[cn][k0];
                bf[nf][1] = Bs[cn][k0 + 4];
            }
            #pragma unroll
            for (int mf = 0; mf < 2; mf++)
                #pragma unroll
                for (int nf = 0; nf < 4; nf++)
                    mma_tf32(acc[mf][nf], af[mf], bf[nf]);
        }

        if (c < 7) {
            __syncthreads();
            #pragma unroll
            for (int i = 0; i < 2; i++)
                *(uint4*)&As[lrow + 32 * i][lf4 * 4] = to_tf32x4(ar[i]);
            #pragma unroll
            for (int i = 0; i < 4; i++)
                *(uint4*)&Bs[lrow + 32 * i][lf4 * 4] = to_tf32x4(br[i]);
            __syncthreads();
        }
    }

    // Epilogue: weighted atomic accumulation into out
    #pragma unroll
    for (int mf = 0; mf < 2; mf++) {
        #pragma unroll
        for (int half = 0; half < 2; half++) {
            int row = wm + mf * 16 + qr + half * 8;
            int pi  = mt * 64 + row;
            if (pi < n) {
                int pr = g_pairs[e * NP + pi];
                float wgt = expert_weights[pr];       // flat [B,S,K] index == pair id
                float* op = out + (size_t)(pr >> 1) * ND + db;
                #pragma unroll
                for (int nf = 0; nf < 4; nf++) {
                    int col = wn + nf * 8 + 2 * qc;
                    atomicAdd(op + col,     wgt * acc[mf][nf][half * 2 + 0]);
                    atomicAdd(op + col + 1, wgt * acc[mf][nf][half * 2 + 1]);
                }
            }
        }
    }
}

extern "C" void kernel_launch(void* const* d_in, const int* in_sizes, int n_in,
                              void* d_out, int out_size) {
    const float* x              = (const float*)d_in[0];
    const float* keys           = (const float*)d_in[1];
    const float* values         = (const float*)d_in[2];
    const float* expert_weights = (const float*)d_in[3];
    const int*   expert_indices = (const int*)d_in[4];
    float* out = (float*)d_out;

    init_kernel<<<NT * ND / 1024, 1024>>>(expert_indices, out);  // zero + bucket

    dim3 g1(NH / 128, NP / 64, NE);     // (8, 16, 16); inactive mtiles exit
    ffn1_mma<<<g1, 256>>>(x, keys);

    dim3 g2(2 * 4, NP / 64, NE);        // (8, 16, 16)
    ffn2_mma<<<g2, 256>>>(values, expert_weights, out);
}